// round 16
// baseline (speedup 1.0000x reference)
#include <cuda_runtime.h>
#include <stdint.h>

#define B 8192
#define D 512
#define AM_THREADS 256
#define AM_GRID 1184   /* 148 SMs x 8 resident blocks, one wave */

__device__ int          g_idx_p[B];
__device__ int          g_idx_n[B];
__device__ float        g_rowloss[B];
__device__ int          g_order[B];
__device__ int          g_base[16];
__device__ unsigned int g_done = 0;

// ---------------- compile-time threefry for key derivation ----------------
struct K2 { uint32_t a, b; };
constexpr uint32_t rotl_c(uint32_t x, int r) { return (x << r) | (x >> (32 - r)); }
constexpr K2 tf_c(uint32_t k0, uint32_t k1, uint32_t x0, uint32_t x1) {
    uint32_t ks2 = k0 ^ k1 ^ 0x1BD11BDAu;
    x0 += k0; x1 += k1;
    const int RA[4] = {13, 15, 26, 6};
    const int RB[4] = {17, 29, 16, 24};
    for (int i = 0; i < 4; i++) { x0 += x1; x1 = rotl_c(x1, RA[i]); x1 ^= x0; }
    x0 += k1;  x1 += ks2 + 1u;
    for (int i = 0; i < 4; i++) { x0 += x1; x1 = rotl_c(x1, RB[i]); x1 ^= x0; }
    x0 += ks2; x1 += k0 + 2u;
    for (int i = 0; i < 4; i++) { x0 += x1; x1 = rotl_c(x1, RA[i]); x1 ^= x0; }
    x0 += k0;  x1 += k1 + 3u;
    for (int i = 0; i < 4; i++) { x0 += x1; x1 = rotl_c(x1, RB[i]); x1 ^= x0; }
    x0 += k1;  x1 += ks2 + 4u;
    for (int i = 0; i < 4; i++) { x0 += x1; x1 = rotl_c(x1, RA[i]); x1 ^= x0; }
    x0 += ks2; x1 += k0 + 5u;
    return K2{x0, x1};
}

constexpr K2 KPk = tf_c(0u, 42u, 0u, 0u);   // split(key(42))[0]
constexpr K2 KNk = tf_c(0u, 42u, 0u, 1u);   // split(key(42))[1]
constexpr uint32_t KP0 = KPk.a, KP1 = KPk.b, KPS = KP0 ^ KP1 ^ 0x1BD11BDAu;
constexpr uint32_t KN0 = KNk.a, KN1 = KNk.b, KNS = KN0 ^ KN1 ^ 0x1BD11BDAu;

#define TFRND(ra) { x0 += x1; x1 = __funnelshift_l(x1, x1, (ra)); x1 ^= x0; }

// Single-chain threefry with compile-time keys (pos loop).
template <uint32_t K0, uint32_t K1, uint32_t KS>
__device__ __forceinline__ uint32_t tf_eval_imm(uint32_t cnt) {
    uint32_t x1 = cnt + K1;
    uint32_t x0 = x1 + K0;
    x1 = __funnelshift_l(x1, x1, 13); x1 ^= x0;
    TFRND(15) TFRND(26) TFRND(6)
    x0 += K1;  x1 += KS + 1u;
    TFRND(17) TFRND(29) TFRND(16) TFRND(24)
    x0 += KS;  x1 += K0 + 2u;
    TFRND(13) TFRND(15) TFRND(26) TFRND(6)
    x0 += K0;  x1 += K1 + 3u;
    TFRND(17) TFRND(29) TFRND(16) TFRND(24)
    x0 += K1;  x1 += KS + 4u;
    TFRND(13) TFRND(15) TFRND(26) TFRND(6)
    x0 += KS;  x1 += K0 + 5u;
    return (x0 ^ x1) & 0xFFFFFE00u;
}

// Two interleaved chains: columns cnt and cnt+1 (neg loop ILP).
#define TF2RND(ra) { \
    a0 += a1; b0 += b1; \
    a1 = __funnelshift_l(a1, a1, (ra)); b1 = __funnelshift_l(b1, b1, (ra)); \
    a1 ^= a0; b1 ^= b0; }

template <uint32_t K0, uint32_t K1, uint32_t KS>
__device__ __forceinline__ void tf_eval_imm2(uint32_t cnt, uint32_t& vA, uint32_t& vB) {
    uint32_t a1 = cnt + K1;
    uint32_t b1 = cnt + (K1 + 1u);     // chain B counter folded as immediate
    uint32_t a0 = a1 + K0;
    uint32_t b0 = b1 + K0;
    a1 = __funnelshift_l(a1, a1, 13); b1 = __funnelshift_l(b1, b1, 13);
    a1 ^= a0; b1 ^= b0;
    TF2RND(15) TF2RND(26) TF2RND(6)
    a0 += K1; b0 += K1; a1 += KS + 1u; b1 += KS + 1u;
    TF2RND(17) TF2RND(29) TF2RND(16) TF2RND(24)
    a0 += KS; b0 += KS; a1 += K0 + 2u; b1 += K0 + 2u;
    TF2RND(13) TF2RND(15) TF2RND(26) TF2RND(6)
    a0 += K0; b0 += K0; a1 += K1 + 3u; b1 += K1 + 3u;
    TF2RND(17) TF2RND(29) TF2RND(16) TF2RND(24)
    a0 += K1; b0 += K1; a1 += KS + 4u; b1 += KS + 4u;
    TF2RND(13) TF2RND(15) TF2RND(26) TF2RND(6)
    a0 += KS; b0 += KS; a1 += K0 + 5u; b1 += K0 + 5u;
    vA = (a0 ^ a1) & 0xFFFFFE00u;
    vB = (b0 ^ b1) & 0xFFFFFE00u;
}

// -------- parallel stable counting sort by label: one block per label ------
__global__ void __launch_bounds__(256) order_kernel(const int* __restrict__ labels) {
    __shared__ int wsum_mine[8];
    __shared__ int wsum_less[8];
    const int w = blockIdx.x;          // this block's label
    const int tid = threadIdx.x;
    const int lane = tid & 31;
    const int wid = tid >> 5;
    const int base_i = tid * 32;       // contiguous 32-element chunk per thread

    int cntLess = 0, cntMine = 0;
    #pragma unroll 8
    for (int i = 0; i < 32; i++) {
        const int l = labels[base_i + i];
        cntLess += (l < w) ? 1 : 0;
        cntMine += (l == w) ? 1 : 0;
    }

    int scan = cntMine;
    for (int off = 1; off < 32; off <<= 1) {
        const int o = __shfl_up_sync(0xFFFFFFFFu, scan, off);
        if (lane >= off) scan += o;
    }
    int lessTot = cntLess;
    for (int off = 16; off > 0; off >>= 1)
        lessTot += __shfl_down_sync(0xFFFFFFFFu, lessTot, off);
    if (lane == 31) wsum_mine[wid] = scan;
    if (lane == 0)  wsum_less[wid] = lessTot;
    __syncthreads();

    int mineBefore = 0, lessAll = 0;
    #pragma unroll
    for (int i = 0; i < 8; i++) {
        if (i < wid) mineBefore += wsum_mine[i];
        lessAll += wsum_less[i];
    }
    int pos = lessAll + (scan - cntMine) + mineBefore;  // stable global slot

    #pragma unroll 8
    for (int i = 0; i < 32; i++) {
        const int idx = base_i + i;
        if (labels[idx] == w) g_order[pos++] = idx;
    }
    if (tid == 0) {
        g_base[w] = lessAll;
        if (w == 0) { g_base[14] = B; g_base[15] = B; }
    }
}

// ---------------- argmax over gumbel-bit matrices (FROZEN, R13/R15 core) ---
__global__ void __launch_bounds__(AM_THREADS, 8) argmax_kernel(const int* __restrict__ labels) {
    __shared__ uint8_t  slab[B];     // 8 KB labels (also read as u16)
    __shared__ uint16_t sord[B];     // 16 KB columns sorted by label
    __shared__ int      sbase[16];
    __shared__ unsigned long long sredp[AM_THREADS / 32];
    __shared__ unsigned long long sredn[AM_THREADS / 32];

    const int tid = threadIdx.x;
    for (int i = tid; i < B; i += AM_THREADS) {
        slab[i] = (uint8_t)labels[i];
        sord[i] = (uint16_t)g_order[i];
    }
    if (tid < 16) sbase[tid] = g_base[tid];
    __syncthreads();

    const uint16_t* slab16 = (const uint16_t*)slab;

    for (int r = blockIdx.x; r < B; r += AM_GRID) {
        const uint32_t myl = slab[r];
        const int posL = sbase[myl];
        const int posR = sbase[myl + 1];
        const uint32_t rB = (uint32_t)r << 13;

        // ---- NEG: 2 interleaved chains on adjacent cols 2*tid+j+512*k ----
        uint32_t bn = 0u;                    // packed: v[31:9] | slotinv[8:4]
        {
            const uint32_t myl2 = myl * 0x0101u;
            const uint32_t cnt_base = rB + 2u * (uint32_t)tid;
            uint32_t kinv = 31u << 4;        // slot = 2k+j, inv = 31-slot
            #pragma unroll 2
            for (uint32_t k = 0; k < 16; k++) {
                const uint32_t labs = (uint32_t)slab16[tid + k * 256];
                const uint32_t t = labs ^ myl2;   // byte j == 0 <=> pos col
                uint32_t vA, vB;
                tf_eval_imm2<KN0, KN1, KNS>(cnt_base + k * 512u, vA, vB);
                vA = (t & 0x00FFu) ? vA : 0u;
                vB = (t & 0xFF00u) ? vB : 0u;
                bn = max(bn, vA | kinv);
                bn = max(bn, vB | (kinv - 16u));
                kinv -= 32u;
            }
        }

        // ---- POS: only same-label columns via sorted list, KP immediates ----
        uint32_t bv = 0u;       // best value
        uint32_t bc = 8191u;    // its column
        {
            const int iters = (posR - posL + (AM_THREADS - 1)) >> 8;
            int j = posL + tid;
            const int last = posR - 1;
            #pragma unroll 1
            for (int kk = 0; kk < iters; kk++) {
                const int i = (j < last) ? j : last;   // clamp tail: duplicate last col
                const uint32_t col = sord[i];
                const uint32_t v = tf_eval_imm<KP0, KP1, KPS>(rB + col);
                // per-thread sequence visits ascending col -> strict > keeps first index
                if (v > bv) { bv = v; bc = col; }
                j += AM_THREADS;
            }
        }

        // ---- merge: u64 (v23<<13)|(8191-col), warp+block argmax ----
        const uint32_t tu = (uint32_t)tid;
        const uint32_t slot = 31u - ((bn >> 4) & 31u);
        const uint32_t coln = 2u * tu + (slot & 1u) + (slot >> 1) * 512u;
        unsigned long long pkn =
            ((unsigned long long)(bn >> 9) << 13) | (unsigned long long)(8191u - coln);
        unsigned long long pkp =
            ((unsigned long long)(bv >> 9) << 13) | (unsigned long long)(8191u - bc);

        for (int off = 16; off > 0; off >>= 1) {
            unsigned long long o;
            o = __shfl_down_sync(0xFFFFFFFFu, pkp, off); if (o > pkp) pkp = o;
            o = __shfl_down_sync(0xFFFFFFFFu, pkn, off); if (o > pkn) pkn = o;
        }
        const int w = tid >> 5;
        if ((tid & 31) == 0) { sredp[w] = pkp; sredn[w] = pkn; }
        __syncthreads();
        if (tid == 0) {
            unsigned long long mp = sredp[0], mn = sredn[0];
            #pragma unroll
            for (int i = 1; i < AM_THREADS / 32; i++) {
                if (sredp[i] > mp) mp = sredp[i];
                if (sredn[i] > mn) mn = sredn[i];
            }
            g_idx_p[r] = 8191 - (int)(mp & 0x1FFFull);
            g_idx_n[r] = 8191 - (int)(mn & 0x1FFFull);
        }
        __syncthreads();
    }
}

// Per-row hinge + fused deterministic final mean (last-block ticket).
__global__ void __launch_bounds__(128) loss_kernel(const float* __restrict__ pred,
                                                   float* __restrict__ out) {
    __shared__ float sred[5][4];
    __shared__ bool  s_last;
    const int r = blockIdx.x;
    const int tid = threadIdx.x;
    const int ip  = g_idx_p[r];
    const int in_ = g_idx_n[r];
    const float4* __restrict__ a4 = (const float4*)(pred + (size_t)r   * D);
    const float4* __restrict__ p4 = (const float4*)(pred + (size_t)ip  * D);
    const float4* __restrict__ n4 = (const float4*)(pred + (size_t)in_ * D);

    const float4 av = a4[tid], pv = p4[tid], nv = n4[tid];
    float saa = av.x*av.x + av.y*av.y + av.z*av.z + av.w*av.w;
    float spp = pv.x*pv.x + pv.y*pv.y + pv.z*pv.z + pv.w*pv.w;
    float snn = nv.x*nv.x + nv.y*nv.y + nv.z*nv.z + nv.w*nv.w;
    float sap = av.x*pv.x + av.y*pv.y + av.z*pv.z + av.w*pv.w;
    float san = av.x*nv.x + av.y*nv.y + av.z*nv.z + av.w*nv.w;

    for (int off = 16; off > 0; off >>= 1) {
        saa += __shfl_down_sync(0xFFFFFFFFu, saa, off);
        spp += __shfl_down_sync(0xFFFFFFFFu, spp, off);
        snn += __shfl_down_sync(0xFFFFFFFFu, snn, off);
        sap += __shfl_down_sync(0xFFFFFFFFu, sap, off);
        san += __shfl_down_sync(0xFFFFFFFFu, san, off);
    }
    const int w = tid >> 5;
    if ((tid & 31) == 0) {
        sred[0][w] = saa; sred[1][w] = spp; sred[2][w] = snn;
        sred[3][w] = sap; sred[4][w] = san;
    }
    __syncthreads();
    if (tid == 0) {
        float t0 = 0, t1 = 0, t2 = 0, t3 = 0, t4 = 0;
        #pragma unroll
        for (int i = 0; i < 4; i++) {
            t0 += sred[0][i]; t1 += sred[1][i]; t2 += sred[2][i];
            t3 += sred[3][i]; t4 += sred[4][i];
        }
        const float na = fmaxf(sqrtf(t0), 1e-6f);
        const float np = fmaxf(sqrtf(t1), 1e-6f);
        const float nn = fmaxf(sqrtf(t2), 1e-6f);
        g_rowloss[r] = fmaxf(t3 / (na * np) - t4 / (na * nn) + 0.1f, 0.0f);
        __threadfence();
        const unsigned int ticket = atomicInc(&g_done, B - 1);  // wraps to 0 at B
        s_last = (ticket == B - 1);
    }
    __syncthreads();

    if (s_last) {
        // deterministic final mean: fixed per-thread order, fixed tree
        __shared__ float s[128];
        const float4* rl = (const float4*)g_rowloss;
        float v = 0.f;
        #pragma unroll
        for (int i = 0; i < 16; i++) {
            const float4 x = rl[tid + i * 128];
            v += (x.x + x.y) + (x.z + x.w);
        }
        s[tid] = v;
        __syncthreads();
        for (int st = 64; st > 0; st >>= 1) {
            if (tid < st) s[tid] += s[tid + st];
            __syncthreads();
        }
        if (tid == 0) out[0] = s[0] * (1.0f / (float)B);
    }
}

extern "C" void kernel_launch(void* const* d_in, const int* in_sizes, int n_in,
                              void* d_out, int out_size) {
    const float* pred   = (const float*)d_in[0];
    const int*   labels = (const int*)d_in[1];
    float* out = (float*)d_out;

    order_kernel<<<14, 256>>>(labels);
    argmax_kernel<<<AM_GRID, AM_THREADS>>>(labels);
    loss_kernel<<<B, 128>>>(pred, out);
}

// round 17
// speedup vs baseline: 1.0325x; 1.0325x over previous
#include <cuda_runtime.h>
#include <stdint.h>

#define B 8192
#define D 512
#define AM_THREADS 256
#define AM_GRID 1184   /* 148 SMs x 8 resident blocks, one wave */

__device__ int   g_idx_p[B];
__device__ int   g_idx_n[B];
__device__ float g_rowloss[B];
__device__ int   g_order[B];
__device__ int   g_base[16];

// ---------------- compile-time threefry for key derivation ----------------
struct K2 { uint32_t a, b; };
constexpr uint32_t rotl_c(uint32_t x, int r) { return (x << r) | (x >> (32 - r)); }
constexpr K2 tf_c(uint32_t k0, uint32_t k1, uint32_t x0, uint32_t x1) {
    uint32_t ks2 = k0 ^ k1 ^ 0x1BD11BDAu;
    x0 += k0; x1 += k1;
    const int RA[4] = {13, 15, 26, 6};
    const int RB[4] = {17, 29, 16, 24};
    for (int i = 0; i < 4; i++) { x0 += x1; x1 = rotl_c(x1, RA[i]); x1 ^= x0; }
    x0 += k1;  x1 += ks2 + 1u;
    for (int i = 0; i < 4; i++) { x0 += x1; x1 = rotl_c(x1, RB[i]); x1 ^= x0; }
    x0 += ks2; x1 += k0 + 2u;
    for (int i = 0; i < 4; i++) { x0 += x1; x1 = rotl_c(x1, RA[i]); x1 ^= x0; }
    x0 += k0;  x1 += k1 + 3u;
    for (int i = 0; i < 4; i++) { x0 += x1; x1 = rotl_c(x1, RB[i]); x1 ^= x0; }
    x0 += k1;  x1 += ks2 + 4u;
    for (int i = 0; i < 4; i++) { x0 += x1; x1 = rotl_c(x1, RA[i]); x1 ^= x0; }
    x0 += ks2; x1 += k0 + 5u;
    return K2{x0, x1};
}

constexpr K2 KPk = tf_c(0u, 42u, 0u, 0u);   // split(key(42))[0]
constexpr K2 KNk = tf_c(0u, 42u, 0u, 1u);   // split(key(42))[1]
constexpr uint32_t KP0 = KPk.a, KP1 = KPk.b, KPS = KP0 ^ KP1 ^ 0x1BD11BDAu;
constexpr uint32_t KN0 = KNk.a, KN1 = KNk.b, KNS = KN0 ^ KN1 ^ 0x1BD11BDAu;

#define TFRND(ra) { x0 += x1; x1 = __funnelshift_l(x1, x1, (ra)); x1 ^= x0; }

// Single-chain threefry with compile-time keys (pos loop).
template <uint32_t K0, uint32_t K1, uint32_t KS>
__device__ __forceinline__ uint32_t tf_eval_imm(uint32_t cnt) {
    uint32_t x1 = cnt + K1;
    uint32_t x0 = x1 + K0;
    x1 = __funnelshift_l(x1, x1, 13); x1 ^= x0;
    TFRND(15) TFRND(26) TFRND(6)
    x0 += K1;  x1 += KS + 1u;
    TFRND(17) TFRND(29) TFRND(16) TFRND(24)
    x0 += KS;  x1 += K0 + 2u;
    TFRND(13) TFRND(15) TFRND(26) TFRND(6)
    x0 += K0;  x1 += K1 + 3u;
    TFRND(17) TFRND(29) TFRND(16) TFRND(24)
    x0 += K1;  x1 += KS + 4u;
    TFRND(13) TFRND(15) TFRND(26) TFRND(6)
    x0 += KS;  x1 += K0 + 5u;
    return (x0 ^ x1) & 0xFFFFFE00u;
}

// Two interleaved chains: columns cnt and cnt+1 (neg loop ILP).
#define TF2RND(ra) { \
    a0 += a1; b0 += b1; \
    a1 = __funnelshift_l(a1, a1, (ra)); b1 = __funnelshift_l(b1, b1, (ra)); \
    a1 ^= a0; b1 ^= b0; }

template <uint32_t K0, uint32_t K1, uint32_t KS>
__device__ __forceinline__ void tf_eval_imm2(uint32_t cnt, uint32_t& vA, uint32_t& vB) {
    uint32_t a1 = cnt + K1;
    uint32_t b1 = cnt + (K1 + 1u);     // chain B counter folded as immediate
    uint32_t a0 = a1 + K0;
    uint32_t b0 = b1 + K0;
    a1 = __funnelshift_l(a1, a1, 13); b1 = __funnelshift_l(b1, b1, 13);
    a1 ^= a0; b1 ^= b0;
    TF2RND(15) TF2RND(26) TF2RND(6)
    a0 += K1; b0 += K1; a1 += KS + 1u; b1 += KS + 1u;
    TF2RND(17) TF2RND(29) TF2RND(16) TF2RND(24)
    a0 += KS; b0 += KS; a1 += K0 + 2u; b1 += K0 + 2u;
    TF2RND(13) TF2RND(15) TF2RND(26) TF2RND(6)
    a0 += K0; b0 += K0; a1 += K1 + 3u; b1 += K1 + 3u;
    TF2RND(17) TF2RND(29) TF2RND(16) TF2RND(24)
    a0 += K1; b0 += K1; a1 += KS + 4u; b1 += KS + 4u;
    TF2RND(13) TF2RND(15) TF2RND(26) TF2RND(6)
    a0 += KS; b0 += KS; a1 += K0 + 5u; b1 += K0 + 5u;
    vA = (a0 ^ a1) & 0xFFFFFE00u;
    vB = (b0 ^ b1) & 0xFFFFFE00u;
}

// -------- parallel stable counting sort by label (coalesced) ---------------
// One block per label. Each warp owns a contiguous 1024-element segment,
// walked lane-strided (coalesced). Stability: segments are in index order,
// ballot-rank preserves order within each 32-wide step.
__global__ void __launch_bounds__(256) order_kernel(const int* __restrict__ labels) {
    __shared__ int warp_mine[8];
    __shared__ int warp_less[8];
    const int w = blockIdx.x;          // this block's label
    const int tid = threadIdx.x;
    const int lane = tid & 31;
    const int wid = tid >> 5;
    const int seg = wid * 1024;        // this warp's contiguous segment

    // pass 1: coalesced counts over the segment
    int mine = 0, less = 0;
    #pragma unroll 8
    for (int i = seg + lane; i < seg + 1024; i += 32) {
        const int l = labels[i];
        mine += (l == w) ? 1 : 0;
        less += (l < w) ? 1 : 0;
    }
    for (int off = 16; off > 0; off >>= 1) {
        mine += __shfl_down_sync(0xFFFFFFFFu, mine, off);
        less += __shfl_down_sync(0xFFFFFFFFu, less, off);
    }
    if (lane == 0) { warp_mine[wid] = mine; warp_less[wid] = less; }
    __syncthreads();

    int lessAll = 0, mineBefore = 0;
    #pragma unroll
    for (int i = 0; i < 8; i++) {
        lessAll += warp_less[i];
        if (i < wid) mineBefore += warp_mine[i];
    }

    // pass 2: coalesced stable ballot-scatter
    int pos = lessAll + mineBefore;
    #pragma unroll 4
    for (int i0 = seg; i0 < seg + 1024; i0 += 32) {
        const int idx = i0 + lane;
        const bool m = (labels[idx] == w);
        const unsigned bal = __ballot_sync(0xFFFFFFFFu, m);
        if (m) g_order[pos + __popc(bal & ((1u << lane) - 1u))] = idx;
        pos += __popc(bal);
    }
    if (tid == 0) {
        g_base[w] = lessAll;
        if (w == 0) { g_base[14] = B; g_base[15] = B; }
    }
}

// ---------------- argmax over gumbel-bit matrices (FROZEN, R13 core) -------
__global__ void __launch_bounds__(AM_THREADS, 8) argmax_kernel(const int* __restrict__ labels) {
    __shared__ uint8_t  slab[B];     // 8 KB labels (also read as u16)
    __shared__ uint16_t sord[B];     // 16 KB columns sorted by label
    __shared__ int      sbase[16];
    __shared__ unsigned long long sredp[AM_THREADS / 32];
    __shared__ unsigned long long sredn[AM_THREADS / 32];

    const int tid = threadIdx.x;
    for (int i = tid; i < B; i += AM_THREADS) {
        slab[i] = (uint8_t)labels[i];
        sord[i] = (uint16_t)g_order[i];
    }
    if (tid < 16) sbase[tid] = g_base[tid];
    __syncthreads();

    const uint16_t* slab16 = (const uint16_t*)slab;

    for (int r = blockIdx.x; r < B; r += AM_GRID) {
        const uint32_t myl = slab[r];
        const int posL = sbase[myl];
        const int posR = sbase[myl + 1];
        const uint32_t rB = (uint32_t)r << 13;

        // ---- NEG: 2 interleaved chains on adjacent cols 2*tid+j+512*k ----
        uint32_t bn = 0u;                    // packed: v[31:9] | slotinv[8:4]
        {
            const uint32_t myl2 = myl * 0x0101u;
            const uint32_t cnt_base = rB + 2u * (uint32_t)tid;
            uint32_t kinv = 31u << 4;        // slot = 2k+j, inv = 31-slot
            #pragma unroll 2
            for (uint32_t k = 0; k < 16; k++) {
                const uint32_t labs = (uint32_t)slab16[tid + k * 256];
                const uint32_t t = labs ^ myl2;   // byte j == 0 <=> pos col
                uint32_t vA, vB;
                tf_eval_imm2<KN0, KN1, KNS>(cnt_base + k * 512u, vA, vB);
                vA = (t & 0x00FFu) ? vA : 0u;
                vB = (t & 0xFF00u) ? vB : 0u;
                bn = max(bn, vA | kinv);
                bn = max(bn, vB | (kinv - 16u));
                kinv -= 32u;
            }
        }

        // ---- POS: only same-label columns via sorted list, KP immediates ----
        uint32_t bv = 0u;       // best value
        uint32_t bc = 8191u;    // its column
        {
            const int iters = (posR - posL + (AM_THREADS - 1)) >> 8;
            int j = posL + tid;
            const int last = posR - 1;
            #pragma unroll 1
            for (int kk = 0; kk < iters; kk++) {
                const int i = (j < last) ? j : last;   // clamp tail: duplicate last col
                const uint32_t col = sord[i];
                const uint32_t v = tf_eval_imm<KP0, KP1, KPS>(rB + col);
                // per-thread sequence visits ascending col -> strict > keeps first index
                if (v > bv) { bv = v; bc = col; }
                j += AM_THREADS;
            }
        }

        // ---- merge: u64 (v23<<13)|(8191-col), warp+block argmax ----
        const uint32_t tu = (uint32_t)tid;
        const uint32_t slot = 31u - ((bn >> 4) & 31u);
        const uint32_t coln = 2u * tu + (slot & 1u) + (slot >> 1) * 512u;
        unsigned long long pkn =
            ((unsigned long long)(bn >> 9) << 13) | (unsigned long long)(8191u - coln);
        unsigned long long pkp =
            ((unsigned long long)(bv >> 9) << 13) | (unsigned long long)(8191u - bc);

        for (int off = 16; off > 0; off >>= 1) {
            unsigned long long o;
            o = __shfl_down_sync(0xFFFFFFFFu, pkp, off); if (o > pkp) pkp = o;
            o = __shfl_down_sync(0xFFFFFFFFu, pkn, off); if (o > pkn) pkn = o;
        }
        const int w = tid >> 5;
        if ((tid & 31) == 0) { sredp[w] = pkp; sredn[w] = pkn; }
        __syncthreads();
        if (tid == 0) {
            unsigned long long mp = sredp[0], mn = sredn[0];
            #pragma unroll
            for (int i = 1; i < AM_THREADS / 32; i++) {
                if (sredp[i] > mp) mp = sredp[i];
                if (sredn[i] > mn) mn = sredn[i];
            }
            g_idx_p[r] = 8191 - (int)(mp & 0x1FFFull);
            g_idx_n[r] = 8191 - (int)(mn & 0x1FFFull);
        }
        __syncthreads();
    }
}

// Per-row hinge: cos(a,p) - cos(a,n) + margin, clamped at 0. float4 loads.
__global__ void __launch_bounds__(128) loss_kernel(const float* __restrict__ pred) {
    __shared__ float sred[5][4];
    const int r = blockIdx.x;
    const int tid = threadIdx.x;
    const int ip  = g_idx_p[r];
    const int in_ = g_idx_n[r];
    const float4* __restrict__ a4 = (const float4*)(pred + (size_t)r   * D);
    const float4* __restrict__ p4 = (const float4*)(pred + (size_t)ip  * D);
    const float4* __restrict__ n4 = (const float4*)(pred + (size_t)in_ * D);

    const float4 av = a4[tid], pv = p4[tid], nv = n4[tid];
    float saa = av.x*av.x + av.y*av.y + av.z*av.z + av.w*av.w;
    float spp = pv.x*pv.x + pv.y*pv.y + pv.z*pv.z + pv.w*pv.w;
    float snn = nv.x*nv.x + nv.y*nv.y + nv.z*nv.z + nv.w*nv.w;
    float sap = av.x*pv.x + av.y*pv.y + av.z*pv.z + av.w*pv.w;
    float san = av.x*nv.x + av.y*nv.y + av.z*nv.z + av.w*nv.w;

    for (int off = 16; off > 0; off >>= 1) {
        saa += __shfl_down_sync(0xFFFFFFFFu, saa, off);
        spp += __shfl_down_sync(0xFFFFFFFFu, spp, off);
        snn += __shfl_down_sync(0xFFFFFFFFu, snn, off);
        sap += __shfl_down_sync(0xFFFFFFFFu, sap, off);
        san += __shfl_down_sync(0xFFFFFFFFu, san, off);
    }
    const int w = tid >> 5;
    if ((tid & 31) == 0) {
        sred[0][w] = saa; sred[1][w] = spp; sred[2][w] = snn;
        sred[3][w] = sap; sred[4][w] = san;
    }
    __syncthreads();
    if (tid == 0) {
        float t0 = 0, t1 = 0, t2 = 0, t3 = 0, t4 = 0;
        #pragma unroll
        for (int i = 0; i < 4; i++) {
            t0 += sred[0][i]; t1 += sred[1][i]; t2 += sred[2][i];
            t3 += sred[3][i]; t4 += sred[4][i];
        }
        const float na = fmaxf(sqrtf(t0), 1e-6f);
        const float np = fmaxf(sqrtf(t1), 1e-6f);
        const float nn = fmaxf(sqrtf(t2), 1e-6f);
        g_rowloss[r] = fmaxf(t3 / (na * np) - t4 / (na * nn) + 0.1f, 0.0f);
    }
}

__global__ void __launch_bounds__(1024) reduce_kernel(float* __restrict__ out) {
    __shared__ float s[1024];
    const int tid = threadIdx.x;
    const float4* rl = (const float4*)g_rowloss;
    float4 v0 = rl[tid];
    float4 v1 = rl[tid + 1024];
    s[tid] = (v0.x + v0.y) + (v0.z + v0.w) + (v1.x + v1.y) + (v1.z + v1.w);
    __syncthreads();
    for (int st = 512; st > 0; st >>= 1) {
        if (tid < st) s[tid] += s[tid + st];
        __syncthreads();
    }
    if (tid == 0) out[0] = s[0] * (1.0f / (float)B);
}

extern "C" void kernel_launch(void* const* d_in, const int* in_sizes, int n_in,
                              void* d_out, int out_size) {
    const float* pred   = (const float*)d_in[0];
    const int*   labels = (const int*)d_in[1];
    float* out = (float*)d_out;

    order_kernel<<<14, 256>>>(labels);
    argmax_kernel<<<AM_GRID, AM_THREADS>>>(labels);
    loss_kernel<<<B, 128>>>(pred);
    reduce_kernel<<<1, 1024>>>(out);
}